// round 1
// baseline (speedup 1.0000x reference)
#include <cuda_runtime.h>
#include <math.h>

// Problem constants
#define B_  4
#define S_  2048
#define D_  1024
#define H_  16
#define HD_ 64
#define M_  (B_ * S_)          // 8192 rows for projections

// ---------------------------------------------------------------------------
// Scratch (device globals; no cudaMalloc allowed)
// ---------------------------------------------------------------------------
__device__ float g_Q[B_ * H_ * S_ * HD_];    // [B,H,S,HD]
__device__ float g_K[B_ * H_ * S_ * HD_];
__device__ float g_V[B_ * H_ * S_ * HD_];
__device__ float g_ctx[B_ * S_ * D_];        // [B*S, D] row-major

// ---------------------------------------------------------------------------
// GEMM: C = A @ W^T + bias
// A: [M, K] row-major, W: [N, K] row-major (torch Linear weight)
// mode 0: write C[m*N + n]               (final out-proj -> d_out)
// mode 1: write [B,H,S,HD] transposed    (QKV projections)
// Tiles: BM=BN=64, BK=16; 256 threads (16x16), 4x4 microtile, strided lanes.
// ---------------------------------------------------------------------------
#define GBM 64
#define GBN 64
#define GBK 16
#define GLD 68   // padded stride (floats)

__global__ void __launch_bounds__(256) gemm_kernel(
    const float* __restrict__ A, const float* __restrict__ W,
    const float* __restrict__ bias, float* __restrict__ C,
    int M, int N, int K, int mode)
{
    __shared__ float As[GBK * GLD];
    __shared__ float Ws[GBK * GLD];

    const int tid = threadIdx.x;
    const int tx = tid & 15;
    const int ty = tid >> 4;

    const int m0 = blockIdx.y * GBM;
    const int n0 = blockIdx.x * GBN;

    // loader indexing: each thread loads one float4 of A-tile and one of W-tile
    const int lr = tid >> 2;          // 0..63  row within tile
    const int lc = (tid & 3) * 4;     // 0,4,8,12 col-within-k-slab

    float acc[4][4];
#pragma unroll
    for (int i = 0; i < 4; i++)
#pragma unroll
        for (int j = 0; j < 4; j++) acc[i][j] = 0.f;

    for (int k0 = 0; k0 < K; k0 += GBK) {
        // load A tile (64 x 16) transposed into As[kk][m]
        float4 av = *reinterpret_cast<const float4*>(&A[(size_t)(m0 + lr) * K + k0 + lc]);
        As[(lc + 0) * GLD + lr] = av.x;
        As[(lc + 1) * GLD + lr] = av.y;
        As[(lc + 2) * GLD + lr] = av.z;
        As[(lc + 3) * GLD + lr] = av.w;
        // load W tile (64 x 16) transposed into Ws[kk][n]
        float4 wv = *reinterpret_cast<const float4*>(&W[(size_t)(n0 + lr) * K + k0 + lc]);
        Ws[(lc + 0) * GLD + lr] = wv.x;
        Ws[(lc + 1) * GLD + lr] = wv.y;
        Ws[(lc + 2) * GLD + lr] = wv.z;
        Ws[(lc + 3) * GLD + lr] = wv.w;
        __syncthreads();

#pragma unroll
        for (int kk = 0; kk < GBK; kk++) {
            float a[4], b[4];
#pragma unroll
            for (int i = 0; i < 4; i++) a[i] = As[kk * GLD + ty + 16 * i];
#pragma unroll
            for (int j = 0; j < 4; j++) b[j] = Ws[kk * GLD + tx + 16 * j];
#pragma unroll
            for (int i = 0; i < 4; i++)
#pragma unroll
                for (int j = 0; j < 4; j++) acc[i][j] += a[i] * b[j];
        }
        __syncthreads();
    }

#pragma unroll
    for (int i = 0; i < 4; i++) {
#pragma unroll
        for (int j = 0; j < 4; j++) {
            int m = m0 + ty + 16 * i;
            int n = n0 + tx + 16 * j;
            float v = acc[i][j] + bias[n];
            if (mode == 0) {
                C[(size_t)m * N + n] = v;
            } else {
                int b  = m / S_;
                int s  = m - b * S_;
                int h  = n >> 6;       // n / 64
                int hd = n & 63;
                C[(((size_t)(b * H_ + h)) * S_ + s) * HD_ + hd] = v;
            }
        }
    }
}

// ---------------------------------------------------------------------------
// RoPE, in-place on g_Q and g_K ([B,H,S,HD]).
// out[i]    = x[i]*cos[i]    - x[i+32]*sin[i]       (i < 32)
// out[i+32] = x[i+32]*cos[i+32] + x[i]*sin[i+32]
// ---------------------------------------------------------------------------
__global__ void rope_kernel(float* __restrict__ Q, float* __restrict__ K,
                            const float* __restrict__ cosp,
                            const float* __restrict__ sinp)
{
    int idx = blockIdx.x * blockDim.x + threadIdx.x;   // (row, i<32)
    if (idx >= B_ * H_ * S_ * 32) return;
    int row = idx >> 5;
    int i   = idx & 31;
    int s   = row & (S_ - 1);     // row % S_  (S_ power of 2)

    float c0 = cosp[s * HD_ + i];
    float s0 = sinp[s * HD_ + i];
    float c1 = cosp[s * HD_ + i + 32];
    float s1 = sinp[s * HD_ + i + 32];

    size_t base = (size_t)row * HD_;
    float q0 = Q[base + i], q1 = Q[base + i + 32];
    Q[base + i]      = q0 * c0 - q1 * s0;
    Q[base + i + 32] = q1 * c1 + q0 * s1;

    float k0v = K[base + i], k1v = K[base + i + 32];
    K[base + i]      = k0v * c0 - k1v * s0;
    K[base + i + 32] = k1v * c1 + k0v * s1;
}

// ---------------------------------------------------------------------------
// Flash attention (fp32, causal). Br = Bc = 64, HD = 64.
// Block: (q-tile, b*h). 256 threads (16x16). Online softmax.
// smem: Qs[64][68], KVs[64][68] (K then reused for V), Ss[64][68], stats.
// ---------------------------------------------------------------------------
#define FLD 68
#define ATT_SMEM ((3 * 64 * FLD + 3 * 64) * 4)

__global__ void __launch_bounds__(256) attn_kernel(
    const float* __restrict__ Q, const float* __restrict__ K,
    const float* __restrict__ V, float* __restrict__ ctx)
{
    extern __shared__ float sm[];
    float* Qs  = sm;                     // 64*68
    float* KVs = Qs + 64 * FLD;          // 64*68
    float* Ss  = KVs + 64 * FLD;         // 64*68
    float* mrow = Ss + 64 * FLD;         // 64
    float* lrow = mrow + 64;             // 64
    float* arow = lrow + 64;             // 64

    const int tid = threadIdx.x;
    const int tx = tid & 15;
    const int ty = tid >> 4;

    const int qt = blockIdx.x;           // q-tile (0..31)
    const int bh = blockIdx.y;           // 0..B*H-1
    const int b  = bh / H_;
    const int h  = bh - b * H_;

    const float* Qp = Q + (size_t)bh * S_ * HD_ + (size_t)qt * 64 * HD_;
    const float* Kp = K + (size_t)bh * S_ * HD_;
    const float* Vp = V + (size_t)bh * S_ * HD_;

    // load Q tile (64x64)
    {
        int r  = tid >> 2;
        int c4 = (tid & 3) * 16;
#pragma unroll
        for (int p = 0; p < 4; p++) {
            float4 v = *reinterpret_cast<const float4*>(&Qp[r * HD_ + c4 + p * 4]);
            *reinterpret_cast<float4*>(&Qs[r * FLD + c4 + p * 4]) = v;
        }
    }
    if (tid < 64) { mrow[tid] = -1e30f; lrow[tid] = 0.f; }

    float Or[4][4];
#pragma unroll
    for (int i = 0; i < 4; i++)
#pragma unroll
        for (int j = 0; j < 4; j++) Or[i][j] = 0.f;

    __syncthreads();

    for (int jt = 0; jt <= qt; jt++) {
        // ---- load K tile ----
        {
            const float* Kt = Kp + (size_t)jt * 64 * HD_;
            int r  = tid >> 2;
            int c4 = (tid & 3) * 16;
#pragma unroll
            for (int p = 0; p < 4; p++) {
                float4 v = *reinterpret_cast<const float4*>(&Kt[r * HD_ + c4 + p * 4]);
                *reinterpret_cast<float4*>(&KVs[r * FLD + c4 + p * 4]) = v;
            }
        }
        __syncthreads();

        // ---- S = Q @ K^T  (64x64x64) ----
        float sacc[4][4];
#pragma unroll
        for (int i = 0; i < 4; i++)
#pragma unroll
            for (int j = 0; j < 4; j++) sacc[i][j] = 0.f;

#pragma unroll
        for (int d4 = 0; d4 < 16; d4++) {
            float4 a[4], bb[4];
#pragma unroll
            for (int i = 0; i < 4; i++)
                a[i] = *reinterpret_cast<const float4*>(&Qs[(ty + 16 * i) * FLD + d4 * 4]);
#pragma unroll
            for (int j = 0; j < 4; j++)
                bb[j] = *reinterpret_cast<const float4*>(&KVs[(tx + 16 * j) * FLD + d4 * 4]);
#pragma unroll
            for (int i = 0; i < 4; i++)
#pragma unroll
                for (int j = 0; j < 4; j++) {
                    sacc[i][j] += a[i].x * bb[j].x;
                    sacc[i][j] += a[i].y * bb[j].y;
                    sacc[i][j] += a[i].z * bb[j].z;
                    sacc[i][j] += a[i].w * bb[j].w;
                }
        }
        // causal mask + scale, write to Ss
#pragma unroll
        for (int i = 0; i < 4; i++) {
#pragma unroll
            for (int j = 0; j < 4; j++) {
                int qg = qt * 64 + ty + 16 * i;
                int kg = jt * 64 + tx + 16 * j;
                float v = (kg <= qg) ? sacc[i][j] * 0.125f : -1e30f;
                Ss[(ty + 16 * i) * FLD + tx + 16 * j] = v;
            }
        }
        __syncthreads();   // S-GEMM done reading KVs; Ss ready

        // ---- softmax row update (one thread per row) ----
        if (tid < 64) {
            int r = tid;
            float mx = -1e30f;
#pragma unroll 8
            for (int k = 0; k < 64; k++) mx = fmaxf(mx, Ss[r * FLD + k]);
            float mnew = fmaxf(mrow[r], mx);
            float sum = 0.f;
#pragma unroll 8
            for (int k = 0; k < 64; k++) {
                float p = __expf(Ss[r * FLD + k] - mnew);
                Ss[r * FLD + k] = p;
                sum += p;
            }
            float al = __expf(mrow[r] - mnew);
            lrow[r] = lrow[r] * al + sum;
            mrow[r] = mnew;
            arow[r] = al;
        }

        // ---- load V tile into KVs (overwrites K; safe after the sync) ----
        {
            const float* Vt = Vp + (size_t)jt * 64 * HD_;
            int r  = tid >> 2;
            int c4 = (tid & 3) * 16;
#pragma unroll
            for (int p = 0; p < 4; p++) {
                float4 v = *reinterpret_cast<const float4*>(&Vt[r * HD_ + c4 + p * 4]);
                *reinterpret_cast<float4*>(&KVs[r * FLD + c4 + p * 4]) = v;
            }
        }
        __syncthreads();   // Ss(probs), arow, V all ready

        // ---- O = O*alpha + P @ V ----
        float al[4];
#pragma unroll
        for (int i = 0; i < 4; i++) al[i] = arow[ty + 16 * i];
#pragma unroll
        for (int i = 0; i < 4; i++)
#pragma unroll
            for (int j = 0; j < 4; j++) Or[i][j] *= al[i];

#pragma unroll 16
        for (int k = 0; k < 64; k++) {
            float a[4], bb[4];
#pragma unroll
            for (int i = 0; i < 4; i++) a[i] = Ss[(ty + 16 * i) * FLD + k];
#pragma unroll
            for (int j = 0; j < 4; j++) bb[j] = KVs[k * FLD + tx + 16 * j];
#pragma unroll
            for (int i = 0; i < 4; i++)
#pragma unroll
                for (int j = 0; j < 4; j++) Or[i][j] += a[i] * bb[j];
        }
        __syncthreads();   // before next tile overwrites KVs / Ss
    }

    // ---- epilogue: normalize and write ctx [B*S, D] row-major ----
#pragma unroll
    for (int i = 0; i < 4; i++) {
        int r = ty + 16 * i;
        float inv = 1.0f / lrow[r];
#pragma unroll
        for (int j = 0; j < 4; j++) {
            int c = tx + 16 * j;
            ctx[((size_t)(b * S_ + qt * 64 + r)) * D_ + h * HD_ + c] = Or[i][j] * inv;
        }
    }
}

// ---------------------------------------------------------------------------
// Launch
// ---------------------------------------------------------------------------
extern "C" void kernel_launch(void* const* d_in, const int* in_sizes, int n_in,
                              void* d_out, int out_size)
{
    const float* x    = (const float*)d_in[0];
    // d_in[1] = mask (causal, recomputed analytically -> unused)
    const float* cosp = (const float*)d_in[2];
    const float* sinp = (const float*)d_in[3];
    const float* Wq   = (const float*)d_in[4];
    const float* bq   = (const float*)d_in[5];
    const float* Wk   = (const float*)d_in[6];
    const float* bk   = (const float*)d_in[7];
    const float* Wv   = (const float*)d_in[8];
    const float* bv   = (const float*)d_in[9];
    const float* Wo   = (const float*)d_in[10];
    const float* bo   = (const float*)d_in[11];
    float* out        = (float*)d_out;

    float *pQ, *pK, *pV, *pC;
    cudaGetSymbolAddress((void**)&pQ, g_Q);
    cudaGetSymbolAddress((void**)&pK, g_K);
    cudaGetSymbolAddress((void**)&pV, g_V);
    cudaGetSymbolAddress((void**)&pC, g_ctx);

    cudaFuncSetAttribute(attn_kernel, cudaFuncAttributeMaxDynamicSharedMemorySize,
                         ATT_SMEM);

    dim3 ggrid(D_ / GBN, M_ / GBM);   // (16, 128)

    // QKV projections (write [B,H,S,HD])
    gemm_kernel<<<ggrid, 256>>>(x, Wq, bq, pQ, M_, D_, D_, 1);
    gemm_kernel<<<ggrid, 256>>>(x, Wk, bk, pK, M_, D_, D_, 1);
    gemm_kernel<<<ggrid, 256>>>(x, Wv, bv, pV, M_, D_, D_, 1);

    // RoPE on Q, K
    {
        int total = B_ * H_ * S_ * 32;
        rope_kernel<<<(total + 255) / 256, 256>>>(pQ, pK, cosp, sinp);
    }

    // attention
    {
        dim3 agrid(S_ / 64, B_ * H_);
        attn_kernel<<<agrid, 256, ATT_SMEM>>>(pQ, pK, pV, pC);
    }

    // output projection -> d_out
    gemm_kernel<<<ggrid, 256>>>(pC, Wo, bo, out, M_, D_, D_, 0);
}

// round 4
// speedup vs baseline: 1.5726x; 1.5726x over previous
#include <cuda_runtime.h>
#include <cuda_bf16.h>
#include <math.h>
#include <stdint.h>

// Problem constants
#define B_  4
#define S_  2048
#define D_  1024
#define H_  16
#define HD_ 64
#define M_  (B_ * S_)          // 8192 rows for projections

// ---------------------------------------------------------------------------
// Scratch (device globals; no cudaMalloc allowed)
// ---------------------------------------------------------------------------
__device__ float g_Q[B_ * H_ * S_ * HD_];    // [B,H,S,HD]
__device__ float g_K[B_ * H_ * S_ * HD_];
__device__ float g_V[B_ * H_ * S_ * HD_];
__device__ float g_ctx[B_ * S_ * D_];        // [B*S, D] row-major

__device__ __nv_bfloat16 g_xhi[M_ * D_];     // bf16-pair split of activations
__device__ __nv_bfloat16 g_xlo[M_ * D_];
__device__ __nv_bfloat16 g_Whi[4 * D_ * D_]; // bf16-pair split of 4 weights
__device__ __nv_bfloat16 g_Wlo[4 * D_ * D_];

// ---------------------------------------------------------------------------
// PTX helpers (base ISA only: cp.async, ldmatrix, mma.sync — no tcgen05)
// ---------------------------------------------------------------------------
__device__ __forceinline__ uint32_t smem_u32(const void* p) {
    uint32_t a;
    asm("{ .reg .u64 t; cvta.to.shared.u64 t, %1; cvt.u32.u64 %0, t; }"
        : "=r"(a) : "l"(p));
    return a;
}

__device__ __forceinline__ void cp16(uint32_t dst, const void* src) {
    asm volatile("cp.async.cg.shared.global [%0], [%1], 16;"
                 :: "r"(dst), "l"(src));
}
#define CP_COMMIT() asm volatile("cp.async.commit_group;" ::: "memory")
template <int N>
__device__ __forceinline__ void cp_wait() {
    asm volatile("cp.async.wait_group %0;" :: "n"(N) : "memory");
}

__device__ __forceinline__ void ldm_x4(uint32_t& r0, uint32_t& r1,
                                       uint32_t& r2, uint32_t& r3, uint32_t addr) {
    asm volatile("ldmatrix.sync.aligned.m8n8.x4.shared.b16 {%0,%1,%2,%3}, [%4];"
                 : "=r"(r0), "=r"(r1), "=r"(r2), "=r"(r3) : "r"(addr));
}

__device__ __forceinline__ void mma_bf16(float* d, uint32_t a0, uint32_t a1,
                                         uint32_t a2, uint32_t a3,
                                         uint32_t b0, uint32_t b1) {
    asm volatile(
        "mma.sync.aligned.m16n8k16.row.col.f32.bf16.bf16.f32 "
        "{%0,%1,%2,%3}, {%4,%5,%6,%7}, {%8,%9}, {%0,%1,%2,%3};"
        : "+f"(d[0]), "+f"(d[1]), "+f"(d[2]), "+f"(d[3])
        : "r"(a0), "r"(a1), "r"(a2), "r"(a3), "r"(b0), "r"(b1));
}

// ---------------------------------------------------------------------------
// split: x -> (hi, lo) bf16 pair, float4 granularity
// ---------------------------------------------------------------------------
__global__ void split_kernel(const float* __restrict__ src,
                             __nv_bfloat16* __restrict__ hi,
                             __nv_bfloat16* __restrict__ lo, int n4)
{
    int i = blockIdx.x * blockDim.x + threadIdx.x;
    if (i >= n4) return;
    float4 v = reinterpret_cast<const float4*>(src)[i];
    __nv_bfloat16 hx = __float2bfloat16(v.x);
    __nv_bfloat16 hy = __float2bfloat16(v.y);
    __nv_bfloat16 hz = __float2bfloat16(v.z);
    __nv_bfloat16 hw = __float2bfloat16(v.w);
    __nv_bfloat16 lx = __float2bfloat16(v.x - __bfloat162float(hx));
    __nv_bfloat16 ly = __float2bfloat16(v.y - __bfloat162float(hy));
    __nv_bfloat16 lz = __float2bfloat16(v.z - __bfloat162float(hz));
    __nv_bfloat16 lw = __float2bfloat16(v.w - __bfloat162float(hw));
    __nv_bfloat162* hp = reinterpret_cast<__nv_bfloat162*>(hi);
    __nv_bfloat162* lp = reinterpret_cast<__nv_bfloat162*>(lo);
    hp[2 * i]     = __nv_bfloat162(hx, hy);
    hp[2 * i + 1] = __nv_bfloat162(hz, hw);
    lp[2 * i]     = __nv_bfloat162(lx, ly);
    lp[2 * i + 1] = __nv_bfloat162(lz, lw);
}

// ---------------------------------------------------------------------------
// mma.sync GEMM: C = A @ W^T + bias via bf16-pair 3-segment decomposition.
// A: [8192,1024] (hi/lo), W: [1024,1024] (hi/lo), both K-major row-major.
// CTA tile 128x128, BK=32, 8 warps (4 m x 2 n), warp tile 32x64.
// 4-stage cp.async ring. Smem rows padded to 80B (ldmatrix conflict-free).
// mode 0: C[m*1024+n]; mode 1: scatter to [B,H,S,HD].
// ---------------------------------------------------------------------------
#define TM 128
#define TN 128
#define BK 32
#define NC 96                        // 3 segments * (1024/32)
#define ROWB 80                      // bytes per smem row (32 bf16 + 8 pad)
#define A_BYTES (TM * ROWB)          // 10240
#define STAGE_BYTES (2 * A_BYTES)    // 20480 (A tile + B tile)
#define NSTAGE 4
#define GEMM_DYN_SMEM (NSTAGE * STAGE_BYTES)

__device__ __forceinline__ void load_tile(
    int tid, int m0, int n0, uint32_t smem_base, int c,
    const __nv_bfloat16* Ahi, const __nv_bfloat16* Alo,
    const __nv_bfloat16* Whi, const __nv_bfloat16* Wlo)
{
    int s   = c & (NSTAGE - 1);
    int seg = c >> 5;                 // 0: hi*hi, 1: hi*lo, 2: lo*hi
    int kb  = (c & 31) * BK;          // k offset (elements)
    const char* ap = (const char*)((seg == 2) ? Alo : Ahi);
    const char* bp = (const char*)((seg == 1) ? Wlo : Whi);
    uint32_t abase = smem_base + s * STAGE_BYTES;
    uint32_t bbase = abase + A_BYTES;
#pragma unroll
    for (int i = 0; i < 2; i++) {
        int cidx = tid + i * 256;     // 0..511
        int row  = cidx >> 2;
        int g    = cidx & 3;
        cp16(abase + row * ROWB + g * 16,
             ap + ((size_t)(m0 + row) * 1024 + kb) * 2 + g * 16);
    }
#pragma unroll
    for (int i = 0; i < 2; i++) {
        int cidx = tid + i * 256;
        int row  = cidx >> 2;
        int g    = cidx & 3;
        cp16(bbase + row * ROWB + g * 16,
             bp + ((size_t)(n0 + row) * 1024 + kb) * 2 + g * 16);
    }
    CP_COMMIT();
}

__global__ void __launch_bounds__(256, 1) gemm_tc(
    const __nv_bfloat16* __restrict__ Ahi, const __nv_bfloat16* __restrict__ Alo,
    const __nv_bfloat16* __restrict__ Whi, const __nv_bfloat16* __restrict__ Wlo,
    const float* __restrict__ bias, float* __restrict__ C, int mode)
{
    extern __shared__ char dyn[];
    __shared__ float bias_s[TN];

    const int tid = threadIdx.x;
    const int wid = tid >> 5;
    const int lid = tid & 31;
    const int wm  = wid >> 1;         // 0..3
    const int wn  = wid & 1;          // 0..1
    const int n0 = blockIdx.x * TN;
    const int m0 = blockIdx.y * TM;

    uint32_t smem_base = smem_u32(dyn);
    if (tid < TN) bias_s[tid] = bias[n0 + tid];

    float acc[2][8][4];
#pragma unroll
    for (int mt = 0; mt < 2; mt++)
#pragma unroll
        for (int na = 0; na < 8; na++)
#pragma unroll
            for (int q = 0; q < 4; q++) acc[mt][na][q] = 0.f;

    // prologue
    load_tile(tid, m0, n0, smem_base, 0, Ahi, Alo, Whi, Wlo);
    load_tile(tid, m0, n0, smem_base, 1, Ahi, Alo, Whi, Wlo);
    load_tile(tid, m0, n0, smem_base, 2, Ahi, Alo, Whi, Wlo);

    // ldmatrix lane addressing (constant across iterations)
    const int a_row = ((lid >> 3) & 1) * 8 + (lid & 7);   // + mt*16
    const int a_col = ((lid >> 4) & 1) * 8;               // + ka*16
    const int b_row = ((lid >> 4) & 1) * 8 + (lid & 7);   // + ng*16
    const int b_col = ((lid >> 3) & 1) * 8;               // + ka*16

    for (int c = 0; c < NC; c++) {
        if (c + 3 < NC)
            load_tile(tid, m0, n0, smem_base, c + 3, Ahi, Alo, Whi, Wlo);
        int rem = NC - 1 - c;
        if (rem >= 3)      cp_wait<3>();
        else if (rem == 2) cp_wait<2>();
        else if (rem == 1) cp_wait<1>();
        else               cp_wait<0>();
        __syncthreads();

        uint32_t abase = smem_base + (c & (NSTAGE - 1)) * STAGE_BYTES;
        uint32_t a_warp = abase + wm * 32 * ROWB;
        uint32_t b_warp = abase + A_BYTES + wn * 64 * ROWB;

#pragma unroll
        for (int ka = 0; ka < 2; ka++) {
            uint32_t af[2][4];
#pragma unroll
            for (int mt = 0; mt < 2; mt++) {
                uint32_t addr = a_warp + (mt * 16 + a_row) * ROWB +
                                (ka * 16 + a_col) * 2;
                ldm_x4(af[mt][0], af[mt][1], af[mt][2], af[mt][3], addr);
            }
#pragma unroll
            for (int ng = 0; ng < 4; ng++) {
                uint32_t r0, r1, r2, r3;
                uint32_t addr = b_warp + (ng * 16 + b_row) * ROWB +
                                (ka * 16 + b_col) * 2;
                ldm_x4(r0, r1, r2, r3, addr);
#pragma unroll
                for (int mt = 0; mt < 2; mt++) {
                    mma_bf16(acc[mt][2 * ng],     af[mt][0], af[mt][1],
                             af[mt][2], af[mt][3], r0, r1);
                    mma_bf16(acc[mt][2 * ng + 1], af[mt][0], af[mt][1],
                             af[mt][2], af[mt][3], r2, r3);
                }
            }
        }
        __syncthreads();
    }

    // epilogue: bias + store
    const int r   = lid >> 2;
    const int cp2 = (lid & 3) * 2;
#pragma unroll
    for (int mt = 0; mt < 2; mt++) {
#pragma unroll
        for (int h2 = 0; h2 < 2; h2++) {
            int m = m0 + wm * 32 + mt * 16 + h2 * 8 + r;
#pragma unroll
            for (int na = 0; na < 8; na++) {
                int nl = wn * 64 + na * 8 + cp2;         // 0..127
                int n  = n0 + nl;
                float2 v;
                v.x = acc[mt][na][h2 * 2 + 0] + bias_s[nl];
                v.y = acc[mt][na][h2 * 2 + 1] + bias_s[nl + 1];
                if (mode == 0) {
                    *reinterpret_cast<float2*>(&C[(size_t)m * 1024 + n]) = v;
                } else {
                    int b  = m >> 11;
                    int sq = m & (S_ - 1);
                    int h  = n >> 6;
                    int hd = n & 63;
                    *reinterpret_cast<float2*>(
                        &C[((size_t)(b * H_ + h) * S_ + sq) * HD_ + hd]) = v;
                }
            }
        }
    }
}

// ---------------------------------------------------------------------------
// RoPE, in-place on g_Q and g_K ([B,H,S,HD]).
// ---------------------------------------------------------------------------
__global__ void rope_kernel(float* __restrict__ Q, float* __restrict__ K,
                            const float* __restrict__ cosp,
                            const float* __restrict__ sinp)
{
    int idx = blockIdx.x * blockDim.x + threadIdx.x;
    if (idx >= B_ * H_ * S_ * 32) return;
    int row = idx >> 5;
    int i   = idx & 31;
    int s   = row & (S_ - 1);

    float c0 = cosp[s * HD_ + i];
    float s0 = sinp[s * HD_ + i];
    float c1 = cosp[s * HD_ + i + 32];
    float s1 = sinp[s * HD_ + i + 32];

    size_t base = (size_t)row * HD_;
    float q0 = Q[base + i], q1 = Q[base + i + 32];
    Q[base + i]      = q0 * c0 - q1 * s0;
    Q[base + i + 32] = q1 * c1 + q0 * s1;

    float k0v = K[base + i], k1v = K[base + i + 32];
    K[base + i]      = k0v * c0 - k1v * s0;
    K[base + i + 32] = k1v * c1 + k0v * s1;
}

// ---------------------------------------------------------------------------
// Flash attention (fp32, causal). Br = Bc = 64, HD = 64. (unchanged R1)
// ---------------------------------------------------------------------------
#define FLD 68
#define ATT_SMEM ((3 * 64 * FLD + 3 * 64) * 4)

__global__ void __launch_bounds__(256) attn_kernel(
    const float* __restrict__ Q, const float* __restrict__ K,
    const float* __restrict__ V, float* __restrict__ ctx)
{
    extern __shared__ float sm[];
    float* Qs  = sm;
    float* KVs = Qs + 64 * FLD;
    float* Ss  = KVs + 64 * FLD;
    float* mrow = Ss + 64 * FLD;
    float* lrow = mrow + 64;
    float* arow = lrow + 64;

    const int tid = threadIdx.x;
    const int tx = tid & 15;
    const int ty = tid >> 4;

    const int qt = blockIdx.x;
    const int bh = blockIdx.y;
    const int b  = bh / H_;
    const int h  = bh - b * H_;

    const float* Qp = Q + (size_t)bh * S_ * HD_ + (size_t)qt * 64 * HD_;
    const float* Kp = K + (size_t)bh * S_ * HD_;
    const float* Vp = V + (size_t)bh * S_ * HD_;

    {
        int r  = tid >> 2;
        int c4 = (tid & 3) * 16;
#pragma unroll
        for (int p = 0; p < 4; p++) {
            float4 v = *reinterpret_cast<const float4*>(&Qp[r * HD_ + c4 + p * 4]);
            *reinterpret_cast<float4*>(&Qs[r * FLD + c4 + p * 4]) = v;
        }
    }
    if (tid < 64) { mrow[tid] = -1e30f; lrow[tid] = 0.f; }

    float Or[4][4];
#pragma unroll
    for (int i = 0; i < 4; i++)
#pragma unroll
        for (int j = 0; j < 4; j++) Or[i][j] = 0.f;

    __syncthreads();

    for (int jt = 0; jt <= qt; jt++) {
        {
            const float* Kt = Kp + (size_t)jt * 64 * HD_;
            int r  = tid >> 2;
            int c4 = (tid & 3) * 16;
#pragma unroll
            for (int p = 0; p < 4; p++) {
                float4 v = *reinterpret_cast<const float4*>(&Kt[r * HD_ + c4 + p * 4]);
                *reinterpret_cast<float4*>(&KVs[r * FLD + c4 + p * 4]) = v;
            }
        }
        __syncthreads();

        float sacc[4][4];
#pragma unroll
        for (int i = 0; i < 4; i++)
#pragma unroll
            for (int j = 0; j < 4; j++) sacc[i][j] = 0.f;

#pragma unroll
        for (int d4 = 0; d4 < 16; d4++) {
            float4 a[4], bb[4];
#pragma unroll
            for (int i = 0; i < 4; i++)
                a[i] = *reinterpret_cast<const float4*>(&Qs[(ty + 16 * i) * FLD + d4 * 4]);
#pragma unroll
            for (int j = 0; j < 4; j++)
                bb[j] = *reinterpret_cast<const float4*>(&KVs[(tx + 16 * j) * FLD + d4 * 4]);
#pragma unroll
            for (int i = 0; i < 4; i++)
#pragma unroll
                for (int j = 0; j < 4; j++) {
                    sacc[i][j] += a[i].x * bb[j].x;
                    sacc[i][j] += a[i].y * bb[j].y;
                    sacc[i][j] += a[i].z * bb[j].z;
                    sacc[i][j] += a[i].w * bb[j].w;
                }
        }
#pragma unroll
        for (int i = 0; i < 4; i++) {
#pragma unroll
            for (int j = 0; j < 4; j++) {
                int qg = qt * 64 + ty + 16 * i;
                int kg = jt * 64 + tx + 16 * j;
                float v = (kg <= qg) ? sacc[i][j] * 0.125f : -1e30f;
                Ss[(ty + 16 * i) * FLD + tx + 16 * j] = v;
            }
        }
        __syncthreads();

        if (tid < 64) {
            int r = tid;
            float mx = -1e30f;
#pragma unroll 8
            for (int k = 0; k < 64; k++) mx = fmaxf(mx, Ss[r * FLD + k]);
            float mnew = fmaxf(mrow[r], mx);
            float sum = 0.f;
#pragma unroll 8
            for (int k = 0; k < 64; k++) {
                float p = __expf(Ss[r * FLD + k] - mnew);
                Ss[r * FLD + k] = p;
                sum += p;
            }
            float al = __expf(mrow[r] - mnew);
            lrow[r] = lrow[r] * al + sum;
            mrow[r] = mnew;
            arow[r] = al;
        }

        {
            const float* Vt = Vp + (size_t)jt * 64 * HD_;
            int r  = tid >> 2;
            int c4 = (tid & 3) * 16;
#pragma unroll
            for (int p = 0; p < 4; p++) {
                float4 v = *reinterpret_cast<const float4*>(&Vt[r * HD_ + c4 + p * 4]);
                *reinterpret_cast<float4*>(&KVs[r * FLD + c4 + p * 4]) = v;
            }
        }
        __syncthreads();

        float al[4];
#pragma unroll
        for (int i = 0; i < 4; i++) al[i] = arow[ty + 16 * i];
#pragma unroll
        for (int i = 0; i < 4; i++)
#pragma unroll
            for (int j = 0; j < 4; j++) Or[i][j] *= al[i];

#pragma unroll 16
        for (int k = 0; k < 64; k++) {
            float a[4], bb[4];
#pragma unroll
            for (int i = 0; i < 4; i++) a[i] = Ss[(ty + 16 * i) * FLD + k];
#pragma unroll
            for (int j = 0; j < 4; j++) bb[j] = KVs[k * FLD + tx + 16 * j];
#pragma unroll
            for (int i = 0; i < 4; i++)
#pragma unroll
                for (int j = 0; j < 4; j++) Or[i][j] += a[i] * bb[j];
        }
        __syncthreads();
    }

#pragma unroll
    for (int i = 0; i < 4; i++) {
        int r = ty + 16 * i;
        float inv = 1.0f / lrow[r];
#pragma unroll
        for (int j = 0; j < 4; j++) {
            int c = tx + 16 * j;
            ctx[((size_t)(b * S_ + qt * 64 + r)) * D_ + h * HD_ + c] = Or[i][j] * inv;
        }
    }
}

// ---------------------------------------------------------------------------
// Launch
// ---------------------------------------------------------------------------
extern "C" void kernel_launch(void* const* d_in, const int* in_sizes, int n_in,
                              void* d_out, int out_size)
{
    const float* x    = (const float*)d_in[0];
    const float* cosp = (const float*)d_in[2];
    const float* sinp = (const float*)d_in[3];
    const float* Wq   = (const float*)d_in[4];
    const float* bq   = (const float*)d_in[5];
    const float* Wk   = (const float*)d_in[6];
    const float* bk   = (const float*)d_in[7];
    const float* Wv   = (const float*)d_in[8];
    const float* bv   = (const float*)d_in[9];
    const float* Wo   = (const float*)d_in[10];
    const float* bo   = (const float*)d_in[11];
    float* out        = (float*)d_out;

    float *pQ, *pK, *pV, *pC;
    __nv_bfloat16 *pxh, *pxl, *pWh, *pWl;
    cudaGetSymbolAddress((void**)&pQ, g_Q);
    cudaGetSymbolAddress((void**)&pK, g_K);
    cudaGetSymbolAddress((void**)&pV, g_V);
    cudaGetSymbolAddress((void**)&pC, g_ctx);
    cudaGetSymbolAddress((void**)&pxh, g_xhi);
    cudaGetSymbolAddress((void**)&pxl, g_xlo);
    cudaGetSymbolAddress((void**)&pWh, g_Whi);
    cudaGetSymbolAddress((void**)&pWl, g_Wlo);

    cudaFuncSetAttribute(attn_kernel, cudaFuncAttributeMaxDynamicSharedMemorySize,
                         ATT_SMEM);
    cudaFuncSetAttribute(gemm_tc, cudaFuncAttributeMaxDynamicSharedMemorySize,
                         GEMM_DYN_SMEM);

    const int DD = D_ * D_;

    // split x and weights into bf16 pairs
    split_kernel<<<(M_ * D_ / 4 + 255) / 256, 256>>>(x, pxh, pxl, M_ * D_ / 4);
    split_kernel<<<(DD / 4 + 255) / 256, 256>>>(Wq, pWh + 0 * DD, pWl + 0 * DD, DD / 4);
    split_kernel<<<(DD / 4 + 255) / 256, 256>>>(Wk, pWh + 1 * DD, pWl + 1 * DD, DD / 4);
    split_kernel<<<(DD / 4 + 255) / 256, 256>>>(Wv, pWh + 2 * DD, pWl + 2 * DD, DD / 4);
    split_kernel<<<(DD / 4 + 255) / 256, 256>>>(Wo, pWh + 3 * DD, pWl + 3 * DD, DD / 4);

    dim3 ggrid(D_ / TN, M_ / TM);   // (8, 64)

    // QKV projections (HMMA tensor cores, write [B,H,S,HD])
    gemm_tc<<<ggrid, 256, GEMM_DYN_SMEM>>>(pxh, pxl, pWh + 0 * DD, pWl + 0 * DD, bq, pQ, 1);
    gemm_tc<<<ggrid, 256, GEMM_DYN_SMEM>>>(pxh, pxl, pWh + 1 * DD, pWl + 1 * DD, bk, pK, 1);
    gemm_tc<<<ggrid, 256, GEMM_DYN_SMEM>>>(pxh, pxl, pWh + 2 * DD, pWl + 2 * DD, bv, pV, 1);

    // RoPE on Q, K
    {
        int total = B_ * H_ * S_ * 32;
        rope_kernel<<<(total + 255) / 256, 256>>>(pQ, pK, cosp, sinp);
    }

    // attention (fp32 flash)
    {
        dim3 agrid(S_ / 64, B_ * H_);
        attn_kernel<<<agrid, 256, ATT_SMEM>>>(pQ, pK, pV, pC);
    }

    // split ctx, then output projection -> d_out (reuse x split buffers)
    split_kernel<<<(M_ * D_ / 4 + 255) / 256, 256>>>(pC, pxh, pxl, M_ * D_ / 4);
    gemm_tc<<<ggrid, 256, GEMM_DYN_SMEM>>>(pxh, pxl, pWh + 3 * DD, pWl + 3 * DD, bo, out, 0);
}

// round 6
// speedup vs baseline: 2.3014x; 1.4634x over previous
#include <cuda_runtime.h>
#include <cuda_bf16.h>
#include <math.h>
#include <stdint.h>

// Problem constants
#define B_  4
#define S_  2048
#define D_  1024
#define H_  16
#define HD_ 64
#define M_  (B_ * S_)          // 8192 rows for projections

// ---------------------------------------------------------------------------
// Scratch (device globals; no cudaMalloc allowed)
// ---------------------------------------------------------------------------
__device__ float g_Q[B_ * H_ * S_ * HD_];    // fp32 [B,H,S,HD] (pre-rope)
__device__ float g_K[B_ * H_ * S_ * HD_];

__device__ __nv_bfloat16 g_Qhi[B_ * H_ * S_ * HD_];  // post-rope pairs
__device__ __nv_bfloat16 g_Qlo[B_ * H_ * S_ * HD_];
__device__ __nv_bfloat16 g_Khi[B_ * H_ * S_ * HD_];
__device__ __nv_bfloat16 g_Klo[B_ * H_ * S_ * HD_];
__device__ __nv_bfloat16 g_Vhi[B_ * H_ * S_ * HD_];  // from V-proj epilogue
__device__ __nv_bfloat16 g_Vlo[B_ * H_ * S_ * HD_];

__device__ __nv_bfloat16 g_xhi[M_ * D_];     // activation pairs (x, then ctx)
__device__ __nv_bfloat16 g_xlo[M_ * D_];
__device__ __nv_bfloat16 g_Whi[4 * D_ * D_];
__device__ __nv_bfloat16 g_Wlo[4 * D_ * D_];

// ---------------------------------------------------------------------------
// PTX helpers (base ISA only)
// ---------------------------------------------------------------------------
__device__ __forceinline__ uint32_t smem_u32(const void* p) {
    uint32_t a;
    asm("{ .reg .u64 t; cvta.to.shared.u64 t, %1; cvt.u32.u64 %0, t; }"
        : "=r"(a) : "l"(p));
    return a;
}

__device__ __forceinline__ void cp16(uint32_t dst, const void* src) {
    asm volatile("cp.async.cg.shared.global [%0], [%1], 16;"
                 :: "r"(dst), "l"(src));
}
#define CP_COMMIT() asm volatile("cp.async.commit_group;" ::: "memory")
template <int N>
__device__ __forceinline__ void cp_wait() {
    asm volatile("cp.async.wait_group %0;" :: "n"(N) : "memory");
}

__device__ __forceinline__ void ldm_x4(uint32_t& r0, uint32_t& r1,
                                       uint32_t& r2, uint32_t& r3, uint32_t addr) {
    asm volatile("ldmatrix.sync.aligned.m8n8.x4.shared.b16 {%0,%1,%2,%3}, [%4];"
                 : "=r"(r0), "=r"(r1), "=r"(r2), "=r"(r3) : "r"(addr));
}
__device__ __forceinline__ void ldm_x4_t(uint32_t& r0, uint32_t& r1,
                                         uint32_t& r2, uint32_t& r3, uint32_t addr) {
    asm volatile("ldmatrix.sync.aligned.m8n8.x4.trans.shared.b16 {%0,%1,%2,%3}, [%4];"
                 : "=r"(r0), "=r"(r1), "=r"(r2), "=r"(r3) : "r"(addr));
}

__device__ __forceinline__ void mma_bf16(float* d, uint32_t a0, uint32_t a1,
                                         uint32_t a2, uint32_t a3,
                                         uint32_t b0, uint32_t b1) {
    asm volatile(
        "mma.sync.aligned.m16n8k16.row.col.f32.bf16.bf16.f32 "
        "{%0,%1,%2,%3}, {%4,%5,%6,%7}, {%8,%9}, {%0,%1,%2,%3};"
        : "+f"(d[0]), "+f"(d[1]), "+f"(d[2]), "+f"(d[3])
        : "r"(a0), "r"(a1), "r"(a2), "r"(a3), "r"(b0), "r"(b1));
}

// split two floats into packed bf16x2 (hi) and bf16x2 (lo residual)
__device__ __forceinline__ void split2(float x, float y, uint32_t& hi, uint32_t& lo) {
    __nv_bfloat162 h = __floats2bfloat162_rn(x, y);
    float hx = __low2float(h), hy = __high2float(h);
    __nv_bfloat162 l = __floats2bfloat162_rn(x - hx, y - hy);
    hi = *reinterpret_cast<uint32_t*>(&h);
    lo = *reinterpret_cast<uint32_t*>(&l);
}

// ---------------------------------------------------------------------------
// split: fp32 -> (hi, lo) bf16 pair, float4 granularity
// ---------------------------------------------------------------------------
__global__ void split_kernel(const float* __restrict__ src,
                             __nv_bfloat16* __restrict__ hi,
                             __nv_bfloat16* __restrict__ lo, int n4)
{
    int i = blockIdx.x * blockDim.x + threadIdx.x;
    if (i >= n4) return;
    float4 v = reinterpret_cast<const float4*>(src)[i];
    uint32_t h0, l0, h1, l1;
    split2(v.x, v.y, h0, l0);
    split2(v.z, v.w, h1, l1);
    uint32_t* hp = reinterpret_cast<uint32_t*>(hi);
    uint32_t* lp = reinterpret_cast<uint32_t*>(lo);
    hp[2 * i] = h0; hp[2 * i + 1] = h1;
    lp[2 * i] = l0; lp[2 * i + 1] = l1;
}

// ---------------------------------------------------------------------------
// mma.sync GEMM: C = A @ W^T + bias via bf16-pair 3-segment decomposition.
// mode 0: fp32 C[m*1024+n] ; mode 1: fp32 scatter [B,H,S,HD] ;
// mode 2: bf16 hi/lo pair scatter [B,H,S,HD] (V path)
// ---------------------------------------------------------------------------
#define TM 128
#define TN 128
#define BK 32
#define NC 96
#define ROWB 80
#define A_BYTES (TM * ROWB)
#define STAGE_BYTES (2 * A_BYTES)
#define NSTAGE 4
#define GEMM_DYN_SMEM (NSTAGE * STAGE_BYTES)

__device__ __forceinline__ void load_tile(
    int tid, int m0, int n0, uint32_t smem_base, int c,
    const __nv_bfloat16* Ahi, const __nv_bfloat16* Alo,
    const __nv_bfloat16* Whi, const __nv_bfloat16* Wlo)
{
    int s   = c & (NSTAGE - 1);
    int seg = c >> 5;
    int kb  = (c & 31) * BK;
    const char* ap = (const char*)((seg == 2) ? Alo : Ahi);
    const char* bp = (const char*)((seg == 1) ? Wlo : Whi);
    uint32_t abase = smem_base + s * STAGE_BYTES;
    uint32_t bbase = abase + A_BYTES;
#pragma unroll
    for (int i = 0; i < 2; i++) {
        int cidx = tid + i * 256;
        int row  = cidx >> 2;
        int g    = cidx & 3;
        cp16(abase + row * ROWB + g * 16,
             ap + ((size_t)(m0 + row) * 1024 + kb) * 2 + g * 16);
    }
#pragma unroll
    for (int i = 0; i < 2; i++) {
        int cidx = tid + i * 256;
        int row  = cidx >> 2;
        int g    = cidx & 3;
        cp16(bbase + row * ROWB + g * 16,
             bp + ((size_t)(n0 + row) * 1024 + kb) * 2 + g * 16);
    }
    CP_COMMIT();
}

__global__ void __launch_bounds__(256, 1) gemm_tc(
    const __nv_bfloat16* __restrict__ Ahi, const __nv_bfloat16* __restrict__ Alo,
    const __nv_bfloat16* __restrict__ Whi, const __nv_bfloat16* __restrict__ Wlo,
    const float* __restrict__ bias, float* __restrict__ C,
    __nv_bfloat16* __restrict__ Chi, __nv_bfloat16* __restrict__ Clo, int mode)
{
    extern __shared__ char dyn[];
    __shared__ float bias_s[TN];

    const int tid = threadIdx.x;
    const int wid = tid >> 5;
    const int lid = tid & 31;
    const int wm  = wid >> 1;
    const int wn  = wid & 1;
    const int n0 = blockIdx.x * TN;
    const int m0 = blockIdx.y * TM;

    uint32_t smem_base = smem_u32(dyn);
    if (tid < TN) bias_s[tid] = bias[n0 + tid];

    float acc[2][8][4];
#pragma unroll
    for (int mt = 0; mt < 2; mt++)
#pragma unroll
        for (int na = 0; na < 8; na++)
#pragma unroll
            for (int q = 0; q < 4; q++) acc[mt][na][q] = 0.f;

    load_tile(tid, m0, n0, smem_base, 0, Ahi, Alo, Whi, Wlo);
    load_tile(tid, m0, n0, smem_base, 1, Ahi, Alo, Whi, Wlo);
    load_tile(tid, m0, n0, smem_base, 2, Ahi, Alo, Whi, Wlo);

    const int a_row = ((lid >> 3) & 1) * 8 + (lid & 7);
    const int a_col = ((lid >> 4) & 1) * 8;
    const int b_row = ((lid >> 4) & 1) * 8 + (lid & 7);
    const int b_col = ((lid >> 3) & 1) * 8;

    for (int c = 0; c < NC; c++) {
        if (c + 3 < NC)
            load_tile(tid, m0, n0, smem_base, c + 3, Ahi, Alo, Whi, Wlo);
        int rem = NC - 1 - c;
        if (rem >= 3)      cp_wait<3>();
        else if (rem == 2) cp_wait<2>();
        else if (rem == 1) cp_wait<1>();
        else               cp_wait<0>();
        __syncthreads();

        uint32_t abase = smem_base + (c & (NSTAGE - 1)) * STAGE_BYTES;
        uint32_t a_warp = abase + wm * 32 * ROWB;
        uint32_t b_warp = abase + A_BYTES + wn * 64 * ROWB;

#pragma unroll
        for (int ka = 0; ka < 2; ka++) {
            uint32_t af[2][4];
#pragma unroll
            for (int mt = 0; mt < 2; mt++) {
                uint32_t addr = a_warp + (mt * 16 + a_row) * ROWB +
                                (ka * 16 + a_col) * 2;
                ldm_x4(af[mt][0], af[mt][1], af[mt][2], af[mt][3], addr);
            }
#pragma unroll
            for (int ng = 0; ng < 4; ng++) {
                uint32_t r0, r1, r2, r3;
                uint32_t addr = b_warp + (ng * 16 + b_row) * ROWB +
                                (ka * 16 + b_col) * 2;
                ldm_x4(r0, r1, r2, r3, addr);
#pragma unroll
                for (int mt = 0; mt < 2; mt++) {
                    mma_bf16(acc[mt][2 * ng],     af[mt][0], af[mt][1],
                             af[mt][2], af[mt][3], r0, r1);
                    mma_bf16(acc[mt][2 * ng + 1], af[mt][0], af[mt][1],
                             af[mt][2], af[mt][3], r2, r3);
                }
            }
        }
        __syncthreads();
    }

    const int r   = lid >> 2;
    const int cp2 = (lid & 3) * 2;
#pragma unroll
    for (int mt = 0; mt < 2; mt++) {
#pragma unroll
        for (int h2 = 0; h2 < 2; h2++) {
            int m = m0 + wm * 32 + mt * 16 + h2 * 8 + r;
#pragma unroll
            for (int na = 0; na < 8; na++) {
                int nl = wn * 64 + na * 8 + cp2;
                int n  = n0 + nl;
                float vx = acc[mt][na][h2 * 2 + 0] + bias_s[nl];
                float vy = acc[mt][na][h2 * 2 + 1] + bias_s[nl + 1];
                if (mode == 0) {
                    *reinterpret_cast<float2*>(&C[(size_t)m * 1024 + n]) =
                        make_float2(vx, vy);
                } else {
                    int b  = m >> 11;
                    int sq = m & (S_ - 1);
                    int h  = n >> 6;
                    int hd = n & 63;
                    size_t off = ((size_t)(b * H_ + h) * S_ + sq) * HD_ + hd;
                    if (mode == 1) {
                        *reinterpret_cast<float2*>(&C[off]) = make_float2(vx, vy);
                    } else {
                        uint32_t hi, lo;
                        split2(vx, vy, hi, lo);
                        *reinterpret_cast<uint32_t*>(&Chi[off]) = hi;
                        *reinterpret_cast<uint32_t*>(&Clo[off]) = lo;
                    }
                }
            }
        }
    }
}

// ---------------------------------------------------------------------------
// RoPE: read fp32 Q/K, rotate, write bf16 hi/lo pairs.
// ---------------------------------------------------------------------------
__global__ void rope_split_kernel(
    const float* __restrict__ Q, const float* __restrict__ K,
    const float* __restrict__ cosp, const float* __restrict__ sinp,
    __nv_bfloat16* __restrict__ Qhi, __nv_bfloat16* __restrict__ Qlo,
    __nv_bfloat16* __restrict__ Khi, __nv_bfloat16* __restrict__ Klo)
{
    int idx = blockIdx.x * blockDim.x + threadIdx.x;
    if (idx >= B_ * H_ * S_ * 32) return;
    int row = idx >> 5;
    int i   = idx & 31;
    int s   = row & (S_ - 1);

    float c0 = cosp[s * HD_ + i];
    float s0 = sinp[s * HD_ + i];
    float c1 = cosp[s * HD_ + i + 32];
    float s1 = sinp[s * HD_ + i + 32];

    size_t base = (size_t)row * HD_;
    float q0 = Q[base + i], q1 = Q[base + i + 32];
    float qa = q0 * c0 - q1 * s0;
    float qb = q1 * c1 + q0 * s1;
    float k0 = K[base + i], k1 = K[base + i + 32];
    float ka = k0 * c0 - k1 * s0;
    float kb = k1 * c1 + k0 * s1;

    __nv_bfloat16 h;
    h = __float2bfloat16(qa); Qhi[base + i] = h;
    Qlo[base + i] = __float2bfloat16(qa - __bfloat162float(h));
    h = __float2bfloat16(qb); Qhi[base + i + 32] = h;
    Qlo[base + i + 32] = __float2bfloat16(qb - __bfloat162float(h));
    h = __float2bfloat16(ka); Khi[base + i] = h;
    Klo[base + i] = __float2bfloat16(ka - __bfloat162float(h));
    h = __float2bfloat16(kb); Khi[base + i + 32] = h;
    Klo[base + i + 32] = __float2bfloat16(kb - __bfloat162float(h));
}

// ---------------------------------------------------------------------------
// Flash attention on mma.sync bf16 with 3-term pair-split.
// CTA: 64 q-rows, 128 threads (4 warps x 16 rows). Bc=64, double-buffered.
// Output written pre-split into g_xhi/g_xlo at [B*S, D] layout.
// ---------------------------------------------------------------------------
#define AROWB 144                      // 64 bf16 = 128B + 16 pad
#define ATILE (64 * AROWB)             // 9216
#define ASTAGE (4 * ATILE)             // Khi,Klo,Vhi,Vlo
#define ATT_DYN (2 * ATILE + 2 * ASTAGE)   // 92160

__device__ __forceinline__ void att_load_kv(
    int tid, uint32_t stage, int jt,
    const __nv_bfloat16* Khp, const __nv_bfloat16* Klp,
    const __nv_bfloat16* Vhp, const __nv_bfloat16* Vlp)
{
    int row = tid >> 1;
    int gb  = (tid & 1) * 4;
    const __nv_bfloat16* srcs[4] = {
        Khp + (size_t)jt * 64 * HD_, Klp + (size_t)jt * 64 * HD_,
        Vhp + (size_t)jt * 64 * HD_, Vlp + (size_t)jt * 64 * HD_ };
#pragma unroll
    for (int t = 0; t < 4; t++) {
        uint32_t dbase = stage + t * ATILE + row * AROWB;
        const __nv_bfloat16* sp = srcs[t] + row * HD_;
#pragma unroll
        for (int g = 0; g < 4; g++)
            cp16(dbase + (gb + g) * 16, sp + (gb + g) * 8);
    }
    CP_COMMIT();
}

__global__ void __launch_bounds__(128) attn_tc(
    const __nv_bfloat16* __restrict__ Qhi, const __nv_bfloat16* __restrict__ Qlo,
    const __nv_bfloat16* __restrict__ Khi, const __nv_bfloat16* __restrict__ Klo,
    const __nv_bfloat16* __restrict__ Vhi, const __nv_bfloat16* __restrict__ Vlo,
    __nv_bfloat16* __restrict__ Ohi, __nv_bfloat16* __restrict__ Olo)
{
    extern __shared__ char dyn[];
    const int tid = threadIdx.x;
    const int wid = tid >> 5;
    const int lid = tid & 31;
    const int qt = blockIdx.x;
    const int bh = blockIdx.y;
    const int b  = bh >> 4;
    const int h  = bh & 15;

    uint32_t sQhi = smem_u32(dyn);
    uint32_t sQlo = sQhi + ATILE;
    uint32_t sStg = sQlo + ATILE;

    const size_t bh_off = (size_t)bh * S_ * HD_;
    const __nv_bfloat16* Qhp = Qhi + bh_off + (size_t)qt * 64 * HD_;
    const __nv_bfloat16* Qlp = Qlo + bh_off + (size_t)qt * 64 * HD_;
    const __nv_bfloat16* Khp = Khi + bh_off;
    const __nv_bfloat16* Klp = Klo + bh_off;
    const __nv_bfloat16* Vhp = Vhi + bh_off;
    const __nv_bfloat16* Vlp = Vlo + bh_off;

    // load Q tiles (hi/lo)
    {
        int row = tid >> 1;
        int gb  = (tid & 1) * 4;
#pragma unroll
        for (int g = 0; g < 4; g++) {
            cp16(sQhi + row * AROWB + (gb + g) * 16, Qhp + row * HD_ + (gb + g) * 8);
            cp16(sQlo + row * AROWB + (gb + g) * 16, Qlp + row * HD_ + (gb + g) * 8);
        }
        CP_COMMIT();
    }
    att_load_kv(tid, sStg, 0, Khp, Klp, Vhp, Vlp);
    cp_wait<0>();
    __syncthreads();

    // preload Q fragments (constant over kv loop)
    const int a_row = ((lid >> 3) & 1) * 8 + (lid & 7);
    const int a_col = ((lid >> 4) & 1) * 8;
    uint32_t qh[4][4], ql[4][4];
#pragma unroll
    for (int t = 0; t < 4; t++) {
        uint32_t off = (wid * 16 + a_row) * AROWB + (t * 16 + a_col) * 2;
        ldm_x4(qh[t][0], qh[t][1], qh[t][2], qh[t][3], sQhi + off);
        ldm_x4(ql[t][0], ql[t][1], ql[t][2], ql[t][3], sQlo + off);
    }

    float m0 = -1e30f, m1 = -1e30f, l0 = 0.f, l1 = 0.f;
    float oacc[8][4];
#pragma unroll
    for (int n = 0; n < 8; n++)
#pragma unroll
        for (int v = 0; v < 4; v++) oacc[n][v] = 0.f;

    const int kbr = ((lid >> 4) & 1) * 8 + (lid & 7);   // K natom row part
    const int kbc = ((lid >> 3) & 1) * 8;               // K katom col part
    const int vbr = (lid & 7) + ((lid >> 3) & 1) * 8;   // V (trans) key row
    const int vbc = ((lid >> 4) & 1) * 8;               // V hd col part
    const int qrow_g = qt * 64 + wid * 16 + (lid >> 2); // global q row (lo half)

    for (int jt = 0; jt <= qt; jt++) {
        if (jt + 1 <= qt) {
            att_load_kv(tid, sStg + ((jt + 1) & 1) * ASTAGE, jt + 1,
                        Khp, Klp, Vhp, Vlp);
            cp_wait<1>();
        } else {
            cp_wait<0>();
        }
        __syncthreads();

        uint32_t sb   = sStg + (jt & 1) * ASTAGE;
        uint32_t skhi = sb;
        uint32_t sklo = sb + ATILE;
        uint32_t svhi = sb + 2 * ATILE;
        uint32_t svlo = sb + 3 * ATILE;

        // ---- S = Q K^T (3 terms) ----
        float sacc[8][4];
#pragma unroll
        for (int n = 0; n < 8; n++)
#pragma unroll
            for (int v = 0; v < 4; v++) sacc[n][v] = 0.f;

#pragma unroll
        for (int t = 0; t < 4; t++) {
#pragma unroll
            for (int g = 0; g < 4; g++) {
                uint32_t off = (g * 16 + kbr) * AROWB + (t * 16 + kbc) * 2;
                uint32_t b0, b1, b2, b3;
                ldm_x4(b0, b1, b2, b3, skhi + off);
                mma_bf16(sacc[2 * g],     qh[t][0], qh[t][1], qh[t][2], qh[t][3], b0, b1);
                mma_bf16(sacc[2 * g + 1], qh[t][0], qh[t][1], qh[t][2], qh[t][3], b2, b3);
                mma_bf16(sacc[2 * g],     ql[t][0], ql[t][1], ql[t][2], ql[t][3], b0, b1);
                mma_bf16(sacc[2 * g + 1], ql[t][0], ql[t][1], ql[t][2], ql[t][3], b2, b3);
                ldm_x4(b0, b1, b2, b3, sklo + off);
                mma_bf16(sacc[2 * g],     qh[t][0], qh[t][1], qh[t][2], qh[t][3], b0, b1);
                mma_bf16(sacc[2 * g + 1], qh[t][0], qh[t][1], qh[t][2], qh[t][3], b2, b3);
            }
        }

        // ---- scale + causal mask ----
        const bool diag = (jt == qt);
#pragma unroll
        for (int n = 0; n < 8; n++) {
#pragma unroll
            for (int v = 0; v < 4; v++) {
                float sv = sacc[n][v] * 0.125f;
                if (diag) {
                    int kg = jt * 64 + n * 8 + (lid & 3) * 2 + (v & 1);
                    int qg = qrow_g + ((v >= 2) ? 8 : 0);
                    if (kg > qg) sv = -1e30f;
                }
                sacc[n][v] = sv;
            }
        }

        // ---- online softmax (per-quad shuffles; rows r and r+8) ----
        float mx0 = -1e30f, mx1 = -1e30f;
#pragma unroll
        for (int n = 0; n < 8; n++) {
            mx0 = fmaxf(mx0, fmaxf(sacc[n][0], sacc[n][1]));
            mx1 = fmaxf(mx1, fmaxf(sacc[n][2], sacc[n][3]));
        }
        mx0 = fmaxf(mx0, __shfl_xor_sync(0xffffffff, mx0, 1));
        mx0 = fmaxf(mx0, __shfl_xor_sync(0xffffffff, mx0, 2));
        mx1 = fmaxf(mx1, __shfl_xor_sync(0xffffffff, mx1, 1));
        mx1 = fmaxf(mx1, __shfl_xor_sync(0xffffffff, mx1, 2));
        float mn0 = fmaxf(m0, mx0), mn1 = fmaxf(m1, mx1);
        float al0 = __expf(m0 - mn0), al1 = __expf(m1 - mn1);
        m0 = mn0; m1 = mn1;

        float s0 = 0.f, s1 = 0.f;
#pragma unroll
        for (int n = 0; n < 8; n++) {
            float p0 = __expf(sacc[n][0] - mn0);
            float p1 = __expf(sacc[n][1] - mn0);
            float p2 = __expf(sacc[n][2] - mn1);
            float p3 = __expf(sacc[n][3] - mn1);
            sacc[n][0] = p0; sacc[n][1] = p1; sacc[n][2] = p2; sacc[n][3] = p3;
            s0 += p0 + p1; s1 += p2 + p3;
        }
        s0 += __shfl_xor_sync(0xffffffff, s0, 1);
        s0 += __shfl_xor_sync(0xffffffff, s0, 2);
        s1 += __shfl_xor_sync(0xffffffff, s1, 1);
        s1 += __shfl_xor_sync(0xffffffff, s1, 2);
        l0 = l0 * al0 + s0;
        l1 = l1 * al1 + s1;
#pragma unroll
        for (int n = 0; n < 8; n++) {
            oacc[n][0] *= al0; oacc[n][1] *= al0;
            oacc[n][2] *= al1; oacc[n][3] *= al1;
        }

        // ---- O += P V (3 terms); P split per k-atom ----
#pragma unroll
        for (int t = 0; t < 4; t++) {
            uint32_t ph[4], pl[4];
            split2(sacc[2 * t][0],     sacc[2 * t][1],     ph[0], pl[0]);
            split2(sacc[2 * t][2],     sacc[2 * t][3],     ph[1], pl[1]);
            split2(sacc[2 * t + 1][0], sacc[2 * t + 1][1], ph[2], pl[2]);
            split2(sacc[2 * t + 1][2], sacc[2 * t + 1][3], ph[3], pl[3]);
#pragma unroll
            for (int u = 0; u < 4; u++) {
                uint32_t off = (t * 16 + vbr) * AROWB + (u * 16 + vbc) * 2;
                uint32_t v0, v1, v2, v3;
                ldm_x4_t(v0, v1, v2, v3, svhi + off);
                mma_bf16(oacc[2 * u],     ph[0], ph[1], ph[2], ph[3], v0, v1);
                mma_bf16(oacc[2 * u + 1], ph[0], ph[1], ph[2], ph[3], v2, v3);
                mma_bf16(oacc[2 * u],     pl[0], pl[1], pl[2], pl[3], v0, v1);
                mma_bf16(oacc[2 * u + 1], pl[0], pl[1], pl[2], pl[3], v2, v3);
                ldm_x4_t(v0, v1, v2, v3, svlo + off);
                mma_bf16(oacc[2 * u],     ph[0], ph[1], ph[2], ph[3], v0, v1);
                mma_bf16(oacc[2 * u + 1], ph[0], ph[1], ph[2], ph[3], v2, v3);
            }
        }
        __syncthreads();
    }

    // ---- epilogue: normalize, split, write to [B*S, D] ----
    float inv0 = 1.0f / l0, inv1 = 1.0f / l1;
    int srow = qt * 64 + wid * 16 + (lid >> 2);
    size_t base0 = ((size_t)b * S_ + srow) * D_ + h * HD_;
    size_t base1 = base0 + (size_t)8 * D_;
#pragma unroll
    for (int n = 0; n < 8; n++) {
        int c = n * 8 + (lid & 3) * 2;
        uint32_t hi, lo;
        split2(oacc[n][0] * inv0, oacc[n][1] * inv0, hi, lo);
        *reinterpret_cast<uint32_t*>(&Ohi[base0 + c]) = hi;
        *reinterpret_cast<uint32_t*>(&Olo[base0 + c]) = lo;
        split2(oacc[n][2] * inv1, oacc[n][3] * inv1, hi, lo);
        *reinterpret_cast<uint32_t*>(&Ohi[base1 + c]) = hi;
        *reinterpret_cast<uint32_t*>(&Olo[base1 + c]) = lo;
    }
}

// ---------------------------------------------------------------------------
// Launch
// ---------------------------------------------------------------------------
extern "C" void kernel_launch(void* const* d_in, const int* in_sizes, int n_in,
                              void* d_out, int out_size)
{
    const float* x    = (const float*)d_in[0];
    const float* cosp = (const float*)d_in[2];
    const float* sinp = (const float*)d_in[3];
    const float* Wq   = (const float*)d_in[4];
    const float* bq   = (const float*)d_in[5];
    const float* Wk   = (const float*)d_in[6];
    const float* bk   = (const float*)d_in[7];
    const float* Wv   = (const float*)d_in[8];
    const float* bv   = (const float*)d_in[9];
    const float* Wo   = (const float*)d_in[10];
    const float* bo   = (const float*)d_in[11];
    float* out        = (float*)d_out;

    float *pQ, *pK;
    __nv_bfloat16 *pxh, *pxl, *pWh, *pWl;
    __nv_bfloat16 *pQh, *pQl, *pKh, *pKl, *pVh, *pVl;
    cudaGetSymbolAddress((void**)&pQ, g_Q);
    cudaGetSymbolAddress((void**)&pK, g_K);
    cudaGetSymbolAddress((void**)&pxh, g_xhi);
    cudaGetSymbolAddress((void**)&pxl, g_xlo);
    cudaGetSymbolAddress((void**)&pWh, g_Whi);
    cudaGetSymbolAddress((void**)&pWl, g_Wlo);
    cudaGetSymbolAddress((void**)&pQh, g_Qhi);
    cudaGetSymbolAddress((void**)&pQl, g_Qlo);
    cudaGetSymbolAddress((void**)&pKh, g_Khi);
    cudaGetSymbolAddress((void**)&pKl, g_Klo);
    cudaGetSymbolAddress((void**)&pVh, g_Vhi);
    cudaGetSymbolAddress((void**)&pVl, g_Vlo);

    cudaFuncSetAttribute(gemm_tc, cudaFuncAttributeMaxDynamicSharedMemorySize,
                         GEMM_DYN_SMEM);
    cudaFuncSetAttribute(attn_tc, cudaFuncAttributeMaxDynamicSharedMemorySize,
                         ATT_DYN);

    const int DD = D_ * D_;

    // split x and weights into bf16 pairs
    split_kernel<<<(M_ * D_ / 4 + 255) / 256, 256>>>(x, pxh, pxl, M_ * D_ / 4);
    split_kernel<<<(DD / 4 + 255) / 256, 256>>>(Wq, pWh + 0 * DD, pWl + 0 * DD, DD / 4);
    split_kernel<<<(DD / 4 + 255) / 256, 256>>>(Wk, pWh + 1 * DD, pWl + 1 * DD, DD / 4);
    split_kernel<<<(DD / 4 + 255) / 256, 256>>>(Wv, pWh + 2 * DD, pWl + 2 * DD, DD / 4);
    split_kernel<<<(DD / 4 + 255) / 256, 256>>>(Wo, pWh + 3 * DD, pWl + 3 * DD, DD / 4);

    dim3 ggrid(D_ / TN, M_ / TM);

    // Q/K projections (fp32 scatter for RoPE), V projection (bf16 pair scatter)
    gemm_tc<<<ggrid, 256, GEMM_DYN_SMEM>>>(pxh, pxl, pWh + 0 * DD, pWl + 0 * DD,
                                           bq, pQ, nullptr, nullptr, 1);
    gemm_tc<<<ggrid, 256, GEMM_DYN_SMEM>>>(pxh, pxl, pWh + 1 * DD, pWl + 1 * DD,
                                           bk, pK, nullptr, nullptr, 1);
    gemm_tc<<<ggrid, 256, GEMM_DYN_SMEM>>>(pxh, pxl, pWh + 2 * DD, pWl + 2 * DD,
                                           bv, nullptr, pVh, pVl, 2);

    // RoPE -> bf16 pairs
    {
        int total = B_ * H_ * S_ * 32;
        rope_split_kernel<<<(total + 255) / 256, 256>>>(pQ, pK, cosp, sinp,
                                                        pQh, pQl, pKh, pKl);
    }

    // attention (tensor cores), writes split output into g_xhi/g_xlo
    {
        dim3 agrid(S_ / 64, B_ * H_);
        attn_tc<<<agrid, 128, ATT_DYN>>>(pQh, pQl, pKh, pKl, pVh, pVl, pxh, pxl);
    }

    // output projection -> d_out
    gemm_tc<<<ggrid, 256, GEMM_DYN_SMEM>>>(pxh, pxl, pWh + 3 * DD, pWl + 3 * DD,
                                           bo, out, nullptr, nullptr, 0);
}

// round 10
// speedup vs baseline: 2.4951x; 1.0842x over previous
#include <cuda_runtime.h>
#include <cuda_bf16.h>
#include <math.h>
#include <stdint.h>

// Problem constants
#define B_  4
#define S_  2048
#define D_  1024
#define H_  16
#define HD_ 64
#define M_  (B_ * S_)

// ---------------------------------------------------------------------------
// Scratch (device globals)
// ---------------------------------------------------------------------------
__device__ __nv_bfloat16 g_Qhi[B_ * H_ * S_ * HD_];
__device__ __nv_bfloat16 g_Qlo[B_ * H_ * S_ * HD_];
__device__ __nv_bfloat16 g_Khi[B_ * H_ * S_ * HD_];
__device__ __nv_bfloat16 g_Klo[B_ * H_ * S_ * HD_];
__device__ __nv_bfloat16 g_Vhi[B_ * H_ * S_ * HD_];
__device__ __nv_bfloat16 g_Vlo[B_ * H_ * S_ * HD_];

__device__ __nv_bfloat16 g_xhi[M_ * D_];
__device__ __nv_bfloat16 g_xlo[M_ * D_];
__device__ __nv_bfloat16 g_Whi[4 * D_ * D_];
__device__ __nv_bfloat16 g_Wlo[4 * D_ * D_];

// ---------------------------------------------------------------------------
// PTX helpers (base ISA only)
// ---------------------------------------------------------------------------
__device__ __forceinline__ uint32_t smem_u32(const void* p) {
    uint32_t a;
    asm("{ .reg .u64 t; cvta.to.shared.u64 t, %1; cvt.u32.u64 %0, t; }"
        : "=r"(a) : "l"(p));
    return a;
}

__device__ __forceinline__ void cp16(uint32_t dst, const void* src) {
    asm volatile("cp.async.cg.shared.global [%0], [%1], 16;"
                 :: "r"(dst), "l"(src));
}
#define CP_COMMIT() asm volatile("cp.async.commit_group;" ::: "memory")
template <int N>
__device__ __forceinline__ void cp_wait() {
    asm volatile("cp.async.wait_group %0;" :: "n"(N) : "memory");
}

__device__ __forceinline__ void ldm_x4(uint32_t& r0, uint32_t& r1,
                                       uint32_t& r2, uint32_t& r3, uint32_t addr) {
    asm volatile("ldmatrix.sync.aligned.m8n8.x4.shared.b16 {%0,%1,%2,%3}, [%4];"
                 : "=r"(r0), "=r"(r1), "=r"(r2), "=r"(r3) : "r"(addr));
}
__device__ __forceinline__ void ldm_x4_t(uint32_t& r0, uint32_t& r1,
                                         uint32_t& r2, uint32_t& r3, uint32_t addr) {
    asm volatile("ldmatrix.sync.aligned.m8n8.x4.trans.shared.b16 {%0,%1,%2,%3}, [%4];"
                 : "=r"(r0), "=r"(r1), "=r"(r2), "=r"(r3) : "r"(addr));
}

__device__ __forceinline__ void mma_bf16(float* d, uint32_t a0, uint32_t a1,
                                         uint32_t a2, uint32_t a3,
                                         uint32_t b0, uint32_t b1) {
    asm volatile(
        "mma.sync.aligned.m16n8k16.row.col.f32.bf16.bf16.f32 "
        "{%0,%1,%2,%3}, {%4,%5,%6,%7}, {%8,%9}, {%0,%1,%2,%3};"
        : "+f"(d[0]), "+f"(d[1]), "+f"(d[2]), "+f"(d[3])
        : "r"(a0), "r"(a1), "r"(a2), "r"(a3), "r"(b0), "r"(b1));
}

__device__ __forceinline__ void split2(float x, float y, uint32_t& hi, uint32_t& lo) {
    __nv_bfloat162 h = __floats2bfloat162_rn(x, y);
    float hx = __low2float(h), hy = __high2float(h);
    __nv_bfloat162 l = __floats2bfloat162_rn(x - hx, y - hy);
    hi = *reinterpret_cast<uint32_t*>(&h);
    lo = *reinterpret_cast<uint32_t*>(&l);
}

// ---------------------------------------------------------------------------
// split kernels
// ---------------------------------------------------------------------------
__global__ void split_kernel(const float* __restrict__ src,
                             __nv_bfloat16* __restrict__ hi,
                             __nv_bfloat16* __restrict__ lo, int n4)
{
    int i = blockIdx.x * blockDim.x + threadIdx.x;
    if (i >= n4) return;
    float4 v = reinterpret_cast<const float4*>(src)[i];
    uint32_t h0, l0, h1, l1;
    split2(v.x, v.y, h0, l0);
    split2(v.z, v.w, h1, l1);
    uint32_t* hp = reinterpret_cast<uint32_t*>(hi);
    uint32_t* lp = reinterpret_cast<uint32_t*>(lo);
    hp[2 * i] = h0; hp[2 * i + 1] = h1;
    lp[2 * i] = l0; lp[2 * i + 1] = l1;
}

__global__ void wsplit_kernel(const float* __restrict__ w0, const float* __restrict__ w1,
                              const float* __restrict__ w2, const float* __restrict__ w3,
                              __nv_bfloat16* __restrict__ hi,
                              __nv_bfloat16* __restrict__ lo)
{
    int i = blockIdx.x * blockDim.x + threadIdx.x;   // 0..DD/4-1
    int wsel = blockIdx.y;
    const float* src = (wsel == 0) ? w0 : (wsel == 1) ? w1 : (wsel == 2) ? w2 : w3;
    size_t off = (size_t)wsel * (D_ * D_ / 4);
    float4 v = reinterpret_cast<const float4*>(src)[i];
    uint32_t h0, l0, h1, l1;
    split2(v.x, v.y, h0, l0);
    split2(v.z, v.w, h1, l1);
    uint32_t* hp = reinterpret_cast<uint32_t*>(hi) + 2 * off;
    uint32_t* lp = reinterpret_cast<uint32_t*>(lo) + 2 * off;
    hp[2 * i] = h0; hp[2 * i + 1] = h1;
    lp[2 * i] = l0; lp[2 * i + 1] = l1;
}

// ---------------------------------------------------------------------------
// mma.sync GEMM, bf16-pair 3-segment. BK=64, 3-stage ring, 1 sync/iter.
// mode 0: fp32 row-major C (out-proj)
// mode 2: bf16 pair scatter [B,H,S,HD]          (V)
// mode 3: RoPE + bf16 pair scatter [B,H,S,HD]   (Q, K)
// ---------------------------------------------------------------------------
#define TM 128
#define TN 128
#define BK 64
#define NCH 48                   // 3 segments * 1024/64
#define GROWB 144                // 128B data + 16 pad
#define GTILE (TM * GROWB)       // 18432
#define GSTAGE (2 * GTILE)       // 36864
#define GNST 3
#define GEMM_DYN_SMEM (GNST * GSTAGE)   // 110592

__device__ __forceinline__ void load_tile(
    int tid, int m0, int n0, uint32_t smem_base, int c, int s,
    const __nv_bfloat16* Ahi, const __nv_bfloat16* Alo,
    const __nv_bfloat16* Whi, const __nv_bfloat16* Wlo)
{
    int seg = c >> 4;                 // 0: hi*hi, 1: hi*lo, 2: lo*hi
    int kb  = (c & 15) * BK;
    const char* ap = (const char*)((seg == 2) ? Alo : Ahi);
    const char* bp = (const char*)((seg == 1) ? Wlo : Whi);
    uint32_t abase = smem_base + s * GSTAGE;
    uint32_t bbase = abase + GTILE;
    int row = tid >> 1;
    int gb  = (tid & 1) * 4;
    const char* arow = ap + ((size_t)(m0 + row) * 1024 + kb) * 2;
    const char* brow = bp + ((size_t)(n0 + row) * 1024 + kb) * 2;
#pragma unroll
    for (int g = 0; g < 4; g++)
        cp16(abase + row * GROWB + (gb + g) * 16, arow + (gb + g) * 16);
#pragma unroll
    for (int g = 0; g < 4; g++)
        cp16(bbase + row * GROWB + (gb + g) * 16, brow + (gb + g) * 16);
    CP_COMMIT();
}

__global__ void __launch_bounds__(256, 2) gemm_tc(
    const __nv_bfloat16* __restrict__ Ahi, const __nv_bfloat16* __restrict__ Alo,
    const __nv_bfloat16* __restrict__ Whi, const __nv_bfloat16* __restrict__ Wlo,
    const float* __restrict__ bias, float* __restrict__ C,
    __nv_bfloat16* __restrict__ Chi, __nv_bfloat16* __restrict__ Clo,
    const float* __restrict__ cosp, const float* __restrict__ sinp, int mode)
{
    extern __shared__ char dyn[];
    __shared__ float bias_s[TN];

    const int tid = threadIdx.x;
    const int wid = tid >> 5;
    const int lid = tid & 31;
    const int wm  = wid >> 1;
    const int wn  = wid & 1;
    const int n0 = blockIdx.x * TN;
    const int m0 = blockIdx.y * TM;

    uint32_t smem_base = smem_u32(dyn);
    if (tid < TN) bias_s[tid] = bias[n0 + tid];

    float acc[2][8][4];
#pragma unroll
    for (int mt = 0; mt < 2; mt++)
#pragma unroll
        for (int na = 0; na < 8; na++)
#pragma unroll
            for (int q = 0; q < 4; q++) acc[mt][na][q] = 0.f;

    load_tile(tid, m0, n0, smem_base, 0, 0, Ahi, Alo, Whi, Wlo);
    load_tile(tid, m0, n0, smem_base, 1, 1, Ahi, Alo, Whi, Wlo);

    const int a_row = ((lid >> 3) & 1) * 8 + (lid & 7);
    const int a_col = ((lid >> 4) & 1) * 8;
    const int b_row = ((lid >> 4) & 1) * 8 + (lid & 7);
    const int b_col = ((lid >> 3) & 1) * 8;

    int s_cur = 0, s_nxt = 2;
    for (int c = 0; c < NCH; c++) {
        if (c >= NCH - 2) cp_wait<0>(); else cp_wait<1>();
        __syncthreads();
        if (c + 2 < NCH)
            load_tile(tid, m0, n0, smem_base, c + 2, s_nxt, Ahi, Alo, Whi, Wlo);

        uint32_t abase  = smem_base + s_cur * GSTAGE;
        uint32_t a_warp = abase + wm * 32 * GROWB;
        uint32_t b_warp = abase + GTILE + wn * 64 * GROWB;

#pragma unroll
        for (int ka = 0; ka < 4; ka++) {
            uint32_t af[2][4];
#pragma unroll
            for (int mt = 0; mt < 2; mt++) {
                uint32_t addr = a_warp + (mt * 16 + a_row) * GROWB +
                                (ka * 16 + a_col) * 2;
                ldm_x4(af[mt][0], af[mt][1], af[mt][2], af[mt][3], addr);
            }
#pragma unroll
            for (int ng = 0; ng < 4; ng++) {
                uint32_t r0, r1, r2, r3;
                uint32_t addr = b_warp + (ng * 16 + b_row) * GROWB +
                                (ka * 16 + b_col) * 2;
                ldm_x4(r0, r1, r2, r3, addr);
#pragma unroll
                for (int mt = 0; mt < 2; mt++) {
                    mma_bf16(acc[mt][2 * ng],     af[mt][0], af[mt][1],
                             af[mt][2], af[mt][3], r0, r1);
                    mma_bf16(acc[mt][2 * ng + 1], af[mt][0], af[mt][1],
                             af[mt][2], af[mt][3], r2, r3);
                }
            }
        }
        s_cur = (s_cur == 2) ? 0 : s_cur + 1;
        s_nxt = (s_nxt == 2) ? 0 : s_nxt + 1;
    }

    // ---- epilogue ----
    const int r   = lid >> 2;
    const int cp2 = (lid & 3) * 2;
#pragma unroll
    for (int mt = 0; mt < 2; mt++) {
#pragma unroll
        for (int h2 = 0; h2 < 2; h2++) {
            int m = m0 + wm * 32 + mt * 16 + h2 * 8 + r;
            float v[16];
#pragma unroll
            for (int na = 0; na < 8; na++) {
                int nl = wn * 64 + na * 8 + cp2;
                v[2 * na]     = acc[mt][na][h2 * 2 + 0] + bias_s[nl];
                v[2 * na + 1] = acc[mt][na][h2 * 2 + 1] + bias_s[nl + 1];
            }
            if (mode == 0) {
#pragma unroll
                for (int na = 0; na < 8; na++) {
                    int n = n0 + wn * 64 + na * 8 + cp2;
                    *reinterpret_cast<float2*>(&C[(size_t)m * 1024 + n]) =
                        make_float2(v[2 * na], v[2 * na + 1]);
                }
            } else {
                int b  = m >> 11;
                int sq = m & (S_ - 1);
                if (mode == 3) {
                    const float* cr = cosp + sq * HD_;
                    const float* sr = sinp + sq * HD_;
#pragma unroll
                    for (int na = 0; na < 4; na++) {
                        int hd = na * 8 + cp2;
                        float a0 = v[2 * na],     a1 = v[2 * na + 1];
                        float b0 = v[2 * na + 8], b1 = v[2 * na + 9];
                        v[2 * na]     = a0 * cr[hd]      - b0 * sr[hd];
                        v[2 * na + 1] = a1 * cr[hd + 1]  - b1 * sr[hd + 1];
                        v[2 * na + 8] = b0 * cr[hd + 32] + a0 * sr[hd + 32];
                        v[2 * na + 9] = b1 * cr[hd + 33] + a1 * sr[hd + 33];
                    }
                }
#pragma unroll
                for (int na = 0; na < 8; na++) {
                    int n  = n0 + wn * 64 + na * 8 + cp2;
                    int h  = n >> 6;
                    int hd = n & 63;
                    size_t off = ((size_t)(b * H_ + h) * S_ + sq) * HD_ + hd;
                    uint32_t hi, lo;
                    split2(v[2 * na], v[2 * na + 1], hi, lo);
                    *reinterpret_cast<uint32_t*>(&Chi[off]) = hi;
                    *reinterpret_cast<uint32_t*>(&Clo[off]) = lo;
                }
            }
        }
    }
}

// ---------------------------------------------------------------------------
// Flash attention, mma.sync bf16 3-term. Br=128 (8 warps), Bc=64,
// double-buffered K/V, 1 sync per tile.
// ---------------------------------------------------------------------------
#define AROWB 144
#define AQTILE (128 * AROWB)          // 18432 per Q array
#define AKTILE (64 * AROWB)           // 9216 per KV array
#define ASTAGE (4 * AKTILE)           // 36864 (Khi,Klo,Vhi,Vlo)
#define ATT_DYN (2 * AQTILE + 2 * ASTAGE)   // 110592

__device__ __forceinline__ void att_load_kv(
    int tid, uint32_t stage, int jt,
    const __nv_bfloat16* Khp, const __nv_bfloat16* Klp,
    const __nv_bfloat16* Vhp, const __nv_bfloat16* Vlp)
{
    int row = tid >> 2;               // 0..63
    int gb  = (tid & 3) * 2;          // 0,2,4,6
    size_t goff = (size_t)jt * 64 * HD_ + (size_t)row * HD_;
    const __nv_bfloat16* srcs[4] = { Khp + goff, Klp + goff, Vhp + goff, Vlp + goff };
#pragma unroll
    for (int t = 0; t < 4; t++) {
        uint32_t dbase = stage + t * AKTILE + row * AROWB;
#pragma unroll
        for (int g = 0; g < 2; g++)
            cp16(dbase + (gb + g) * 16, srcs[t] + (gb + g) * 8);
    }
    CP_COMMIT();
}

__global__ void __launch_bounds__(256) attn_tc(
    const __nv_bfloat16* __restrict__ Qhi, const __nv_bfloat16* __restrict__ Qlo,
    const __nv_bfloat16* __restrict__ Khi, const __nv_bfloat16* __restrict__ Klo,
    const __nv_bfloat16* __restrict__ Vhi, const __nv_bfloat16* __restrict__ Vlo,
    __nv_bfloat16* __restrict__ Ohi, __nv_bfloat16* __restrict__ Olo)
{
    extern __shared__ char dyn[];
    const int tid = threadIdx.x;
    const int wid = tid >> 5;
    const int lid = tid & 31;
    const int qt = blockIdx.x;           // 128-row q tile (0..15)
    const int bh = blockIdx.y;
    const int b  = bh >> 4;
    const int h  = bh & 15;

    uint32_t sQhi = smem_u32(dyn);
    uint32_t sQlo = sQhi + AQTILE;
    uint32_t sStg = sQlo + AQTILE;

    const size_t bh_off = (size_t)bh * S_ * HD_;
    const __nv_bfloat16* Qhp = Qhi + bh_off + (size_t)qt * 128 * HD_;
    const __nv_bfloat16* Qlp = Qlo + bh_off + (size_t)qt * 128 * HD_;
    const __nv_bfloat16* Khp = Khi + bh_off;
    const __nv_bfloat16* Klp = Klo + bh_off;
    const __nv_bfloat16* Vhp = Vhi + bh_off;
    const __nv_bfloat16* Vlp = Vlo + bh_off;

    // prologue: Q (128 rows) + KV tile 0
    {
        int row = tid >> 1;
        int gb  = (tid & 1) * 4;
#pragma unroll
        for (int g = 0; g < 4; g++) {
            cp16(sQhi + row * AROWB + (gb + g) * 16, Qhp + (size_t)row * HD_ + (gb + g) * 8);
            cp16(sQlo + row * AROWB + (gb + g) * 16, Qlp + (size_t)row * HD_ + (gb + g) * 8);
        }
        CP_COMMIT();
    }
    att_load_kv(tid, sStg, 0, Khp, Klp, Vhp, Vlp);
    cp_wait<0>();
    __syncthreads();

    // Q fragments (constant over the kv loop)
    const int a_row = ((lid >> 3) & 1) * 8 + (lid & 7);
    const int a_col = ((lid >> 4) & 1) * 8;
    uint32_t qh[4][4], ql[4][4];
#pragma unroll
    for (int t = 0; t < 4; t++) {
        uint32_t off = (wid * 16 + a_row) * AROWB + (t * 16 + a_col) * 2;
        ldm_x4(qh[t][0], qh[t][1], qh[t][2], qh[t][3], sQhi + off);
        ldm_x4(ql[t][0], ql[t][1], ql[t][2], ql[t][3], sQlo + off);
    }

    float m0 = -1e30f, m1 = -1e30f, l0 = 0.f, l1 = 0.f;
    float oacc[8][4];
#pragma unroll
    for (int n = 0; n < 8; n++)
#pragma unroll
        for (int v = 0; v < 4; v++) oacc[n][v] = 0.f;

    const int kbr = ((lid >> 4) & 1) * 8 + (lid & 7);
    const int kbc = ((lid >> 3) & 1) * 8;
    const int vbr = (lid & 7) + ((lid >> 3) & 1) * 8;
    const int vbc = ((lid >> 4) & 1) * 8;
    const int qrow_g = qt * 128 + wid * 16 + (lid >> 2);

    const int nt = 2 * qt + 2;
    for (int jt = 0; jt < nt; jt++) {
        if (jt > 0) {
            cp_wait<0>();
            __syncthreads();
        }
        if (jt + 1 < nt)
            att_load_kv(tid, sStg + ((jt + 1) & 1) * ASTAGE, jt + 1,
                        Khp, Klp, Vhp, Vlp);

        uint32_t sb   = sStg + (jt & 1) * ASTAGE;
        uint32_t skhi = sb;
        uint32_t sklo = sb + AKTILE;
        uint32_t svhi = sb + 2 * AKTILE;
        uint32_t svlo = sb + 3 * AKTILE;

        // ---- S = Q K^T (3 terms) ----
        float sacc[8][4];
#pragma unroll
        for (int n = 0; n < 8; n++)
#pragma unroll
            for (int v = 0; v < 4; v++) sacc[n][v] = 0.f;

#pragma unroll
        for (int t = 0; t < 4; t++) {
#pragma unroll
            for (int g = 0; g < 4; g++) {
                uint32_t off = (g * 16 + kbr) * AROWB + (t * 16 + kbc) * 2;
                uint32_t b0, b1, b2, b3;
                ldm_x4(b0, b1, b2, b3, skhi + off);
                mma_bf16(sacc[2 * g],     qh[t][0], qh[t][1], qh[t][2], qh[t][3], b0, b1);
                mma_bf16(sacc[2 * g + 1], qh[t][0], qh[t][1], qh[t][2], qh[t][3], b2, b3);
                mma_bf16(sacc[2 * g],     ql[t][0], ql[t][1], ql[t][2], ql[t][3], b0, b1);
                mma_bf16(sacc[2 * g + 1], ql[t][0], ql[t][1], ql[t][2], ql[t][3], b2, b3);
                ldm_x4(b0, b1, b2, b3, sklo + off);
                mma_bf16(sacc[2 * g],     qh[t][0], qh[t][1], qh[t][2], qh[t][3], b0, b1);
                mma_bf16(sacc[2 * g + 1], qh[t][0], qh[t][1], qh[t][2], qh[t][3], b2, b3);
            }
        }

        // ---- scale + causal mask ----
        const bool maybe_mask = (jt >= 2 * qt);
#pragma unroll
        for (int n = 0; n < 8; n++) {
#pragma unroll
            for (int v = 0; v < 4; v++) {
                float sv = sacc[n][v] * 0.125f;
                if (maybe_mask) {
                    int kg = jt * 64 + n * 8 + (lid & 3) * 2 + (v & 1);
                    int qg = qrow_g + ((v >= 2) ? 8 : 0);
                    if (kg > qg) sv = -1e30f;
                }
                sacc[n][v] = sv;
            }
        }

        // ---- online softmax (quad shuffles) ----
        float mx0 = -1e30f, mx1 = -1e30f;
#pragma unroll
        for (int n = 0; n < 8; n++) {
            mx0 = fmaxf(mx0, fmaxf(sacc[n][0], sacc[n][1]));
            mx1 = fmaxf(mx1, fmaxf(sacc[n][2], sacc[n][3]));
        }
        mx0 = fmaxf(mx0, __shfl_xor_sync(0xffffffff, mx0, 1));
        mx0 = fmaxf(mx0, __shfl_xor_sync(0xffffffff, mx0, 2));
        mx1 = fmaxf(mx1, __shfl_xor_sync(0xffffffff, mx1, 1));
        mx1 = fmaxf(mx1, __shfl_xor_sync(0xffffffff, mx1, 2));
        float mn0 = fmaxf(m0, mx0), mn1 = fmaxf(m1, mx1);
        float al0 = __expf(m0 - mn0), al1 = __expf(m1 - mn1);
        m0 = mn0; m1 = mn1;

        float s0 = 0.f, s1 = 0.f;
#pragma unroll
        for (int n = 0; n < 8; n++) {
            float p0 = __expf(sacc[n][0] - mn0);
            float p1 = __expf(sacc[n][1] - mn0);
            float p2 = __expf(sacc[n][2] - mn1);
            float p3 = __expf(sacc[n][3] - mn1);
            sacc[n][0] = p0; sacc[n][1] = p1; sacc[n][2] = p2; sacc[n][3] = p3;
            s0 += p0 + p1; s1 += p2 + p3;
        }
        s0 += __shfl_xor_sync(0xffffffff, s0, 1);
        s0 += __shfl_xor_sync(0xffffffff, s0, 2);
        s1 += __shfl_xor_sync(0xffffffff, s1, 1);
        s1 += __shfl_xor_sync(0xffffffff, s1, 2);
        l0 = l0 * al0 + s0;
        l1 = l1 * al1 + s1;
#pragma unroll
        for (int n = 0; n < 8; n++) {
            oacc[n][0] *= al0; oacc[n][1] *= al0;
            oacc[n][2] *= al1; oacc[n][3] *= al1;
        }

        // ---- O += P V (3 terms) ----
#pragma unroll
        for (int t = 0; t < 4; t++) {
            uint32_t ph[4], pl[4];
            split2(sacc[2 * t][0],     sacc[2 * t][1],     ph[0], pl[0]);
            split2(sacc[2 * t][2],     sacc[2 * t][3],     ph[1], pl[1]);
            split2(sacc[2 * t + 1][0], sacc[2 * t + 1][1], ph[2], pl[2]);
            split2(sacc[2 * t + 1][2], sacc[2 * t + 1][3], ph[3], pl[3]);
#pragma unroll
            for (int u = 0; u < 4; u++) {
                uint32_t off = (t * 16 + vbr) * AROWB + (u * 16 + vbc) * 2;
                uint32_t v0, v1, v2, v3;
                ldm_x4_t(v0, v1, v2, v3, svhi + off);
                mma_bf16(oacc[2 * u],     ph[0], ph[1], ph[2], ph[3], v0, v1);
                mma_bf16(oacc[2 * u + 1], ph[0], ph[1], ph[2], ph[3], v2, v3);
                mma_bf16(oacc[2 * u],     pl[0], pl[1], pl[2], pl[3], v0, v1);
                mma_bf16(oacc[2 * u + 1], pl[0], pl[1], pl[2], pl[3], v2, v3);
                ldm_x4_t(v0, v1, v2, v3, svlo + off);
                mma_bf16(oacc[2 * u],     ph[0], ph[1], ph[2], ph[3], v0, v1);
                mma_bf16(oacc[2 * u + 1], ph[0], ph[1], ph[2], ph[3], v2, v3);
            }
        }
    }

    // ---- epilogue ----
    float inv0 = 1.0f / l0, inv1 = 1.0f / l1;
    int srow = qt * 128 + wid * 16 + (lid >> 2);
    size_t base0 = ((size_t)b * S_ + srow) * D_ + h * HD_;
    size_t base1 = base0 + (size_t)8 * D_;
#pragma unroll
    for (int n = 0; n < 8; n++) {
        int c = n * 8 + (lid & 3) * 2;
        uint32_t hi, lo;
        split2(oacc[n][0] * inv0, oacc[n][1] * inv0, hi, lo);
        *reinterpret_cast<uint32_t*>(&Ohi[base0 + c]) = hi;
        *reinterpret_cast<uint32_t*>(&Olo[base0 + c]) = lo;
        split2(oacc[n][2] * inv1, oacc[n][3] * inv1, hi, lo);
        *reinterpret_cast<uint32_t*>(&Ohi[base1 + c]) = hi;
        *reinterpret_cast<uint32_t*>(&Olo[base1 + c]) = lo;
    }
}

// ---------------------------------------------------------------------------
// Launch
// ---------------------------------------------------------------------------
extern "C" void kernel_launch(void* const* d_in, const int* in_sizes, int n_in,
                              void* d_out, int out_size)
{
    const float* x    = (const float*)d_in[0];
    const float* cosp = (const float*)d_in[2];
    const float* sinp = (const float*)d_in[3];
    const float* Wq   = (const float*)d_in[4];
    const float* bq   = (const float*)d_in[5];
    const float* Wk   = (const float*)d_in[6];
    const float* bk   = (const float*)d_in[7];
    const float* Wv   = (const float*)d_in[8];
    const float* bv   = (const float*)d_in[9];
    const float* Wo   = (const float*)d_in[10];
    const float* bo   = (const float*)d_in[11];
    float* out        = (float*)d_out;

    __nv_bfloat16 *pxh, *pxl, *pWh, *pWl;
    __nv_bfloat16 *pQh, *pQl, *pKh, *pKl, *pVh, *pVl;
    cudaGetSymbolAddress((void**)&pxh, g_xhi);
    cudaGetSymbolAddress((void**)&pxl, g_xlo);
    cudaGetSymbolAddress((void**)&pWh, g_Whi);
    cudaGetSymbolAddress((void**)&pWl, g_Wlo);
    cudaGetSymbolAddress((void**)&pQh, g_Qhi);
    cudaGetSymbolAddress((void**)&pQl, g_Qlo);
    cudaGetSymbolAddress((void**)&pKh, g_Khi);
    cudaGetSymbolAddress((void**)&pKl, g_Klo);
    cudaGetSymbolAddress((void**)&pVh, g_Vhi);
    cudaGetSymbolAddress((void**)&pVl, g_Vlo);

    cudaFuncSetAttribute(gemm_tc, cudaFuncAttributeMaxDynamicSharedMemorySize,
                         GEMM_DYN_SMEM);
    cudaFuncSetAttribute(attn_tc, cudaFuncAttributeMaxDynamicSharedMemorySize,
                         ATT_DYN);

    const int DD = D_ * D_;

    // activation + weight splits
    split_kernel<<<(M_ * D_ / 4 + 255) / 256, 256>>>(x, pxh, pxl, M_ * D_ / 4);
    {
        dim3 wg((DD / 4 + 255) / 256, 4);
        wsplit_kernel<<<wg, 256>>>(Wq, Wk, Wv, Wo, pWh, pWl);
    }

    dim3 ggrid(D_ / TN, M_ / TM);   // (8, 64)

    // Q/K projections with fused RoPE+split; V projection with fused split
    gemm_tc<<<ggrid, 256, GEMM_DYN_SMEM>>>(pxh, pxl, pWh + 0 * DD, pWl + 0 * DD,
                                           bq, nullptr, pQh, pQl, cosp, sinp, 3);
    gemm_tc<<<ggrid, 256, GEMM_DYN_SMEM>>>(pxh, pxl, pWh + 1 * DD, pWl + 1 * DD,
                                           bk, nullptr, pKh, pKl, cosp, sinp, 3);
    gemm_tc<<<ggrid, 256, GEMM_DYN_SMEM>>>(pxh, pxl, pWh + 2 * DD, pWl + 2 * DD,
                                           bv, nullptr, pVh, pVl, nullptr, nullptr, 2);

    // attention (writes split ctx into g_xhi/g_xlo)
    {
        dim3 agrid(S_ / 128, B_ * H_);
        attn_tc<<<agrid, 256, ATT_DYN>>>(pQh, pQl, pKh, pKl, pVh, pVl, pxh, pxl);
    }

    // output projection -> d_out
    gemm_tc<<<ggrid, 256, GEMM_DYN_SMEM>>>(pxh, pxl, pWh + 3 * DD, pWl + 3 * DD,
                                           bo, out, nullptr, nullptr, nullptr, nullptr, 0);
}